// round 1
// baseline (speedup 1.0000x reference)
#include <cuda_runtime.h>
#include <math.h>
#include <stddef.h>

// ---------------------------------------------------------------------------
// GatedDeltaNet  B=2 S=2048 H=2048  HK=16 HV=32 DK=DV=128  conv K=4
// ---------------------------------------------------------------------------
namespace {
constexpr int Bc = 2, Sc = 2048, Hc = 2048;
constexpr int DK = 128, DV = 128, HK = 16, HV = 32, Gc = 2;
constexpr int FQ  = 2*HK*DK + 2*HV*DV;   // 12288
constexpr int FBA = 2*HV;                // 64
constexpr int ROWH = 2*DK + 2*Gc*DV;     // 768 (per-hk row width inside qkvz)
constexpr int BS = Bc*Sc;                // 4096
constexpr float EPS = 1e-6f;
constexpr float QSCALE = 0.08838834764831845f;  // DK^-0.5
}

// ------------------------- scratch (static device mem) ---------------------
__device__ float g_qkvz[(size_t)BS*FQ];      // 201 MB
__device__ float g_ba  [(size_t)BS*FBA];
__device__ float g_q   [(size_t)BS*HK*DK];
__device__ float g_k   [(size_t)BS*HK*DK];
__device__ float g_v   [(size_t)BS*HV*DV];
__device__ float g_g   [(size_t)BS*HV];
__device__ float g_b   [(size_t)BS*HV];
__device__ float g_o   [(size_t)BS*HV*DV];   // o, then y (in place)

// ------------------------- fp32 SGEMM 128x128x8, 8x8/thread ----------------
template<bool GN>
__global__ __launch_bounds__(256) void sgemm128(const float* __restrict__ A,
                                                const float* __restrict__ B,
                                                float* __restrict__ C,
                                                int M, int N, int K) {
    __shared__ float As[8][128];
    __shared__ float Bs[8][128];
    const int tid = threadIdx.x;
    const int bn = blockIdx.x * 128;
    const int bm = blockIdx.y * 128;
    const int tr = (tid >> 4) * 8;
    const int tc = (tid & 15) * 8;
    const int aRow = tid >> 1, aCol = (tid & 1) * 4;
    const int bRow = tid >> 5, bCol = (tid & 31) * 4;
    const float* Ag = A + (size_t)(bm + aRow) * K + aCol;
    const float* Bg = B + (size_t)bRow * N + bn + bCol;
    float acc[8][8];
#pragma unroll
    for (int i = 0; i < 8; i++)
#pragma unroll
        for (int j = 0; j < 8; j++) acc[i][j] = 0.f;

    for (int k0 = 0; k0 < K; k0 += 8) {
        float4 av = *(const float4*)(Ag + k0);
        As[aCol+0][aRow] = av.x; As[aCol+1][aRow] = av.y;
        As[aCol+2][aRow] = av.z; As[aCol+3][aRow] = av.w;
        float4 bv = make_float4(0.f, 0.f, 0.f, 0.f);
        if (!GN || (bn + bCol) < N) bv = *(const float4*)(Bg + (size_t)k0 * N);
        *(float4*)&Bs[bRow][bCol] = bv;
        __syncthreads();
#pragma unroll
        for (int kk = 0; kk < 8; kk++) {
            float4 a0 = *(const float4*)&As[kk][tr];
            float4 a1 = *(const float4*)&As[kk][tr+4];
            float4 b0 = *(const float4*)&Bs[kk][tc];
            float4 b1 = *(const float4*)&Bs[kk][tc+4];
            float a[8]  = {a0.x,a0.y,a0.z,a0.w,a1.x,a1.y,a1.z,a1.w};
            float bb[8] = {b0.x,b0.y,b0.z,b0.w,b1.x,b1.y,b1.z,b1.w};
#pragma unroll
            for (int i = 0; i < 8; i++)
#pragma unroll
                for (int j = 0; j < 8; j++) acc[i][j] = fmaf(a[i], bb[j], acc[i][j]);
        }
        __syncthreads();
    }
#pragma unroll
    for (int i = 0; i < 8; i++) {
        size_t row = (size_t)(bm + tr + i);
#pragma unroll
        for (int j = 0; j < 8; j += 4) {
            if (!GN || (bn + tc + j) < N)
                *(float4*)&C[row * N + bn + tc + j] =
                    make_float4(acc[i][j], acc[i][j+1], acc[i][j+2], acc[i][j+3]);
        }
    }
}

// ------------- conv(K=4)+silu+l2norm for q,k (one block per b,s,hk) --------
__global__ __launch_bounds__(128) void conv_qk_kernel(const float* __restrict__ qkvz,
        const float* __restrict__ cw, const float* __restrict__ cb,
        float* __restrict__ qo, float* __restrict__ ko) {
    int bsh = blockIdx.x;
    int hk = bsh % HK;
    int bs = bsh / HK;
    int s = bs % Sc;
    int d = threadIdx.x;
    int cq = hk*DK + d;
    int ck = HK*DK + cq;
    const float* base = qkvz + (size_t)bs*FQ + hk*ROWH + d;
    float aq = cb[cq], ak = cb[ck];
#pragma unroll
    for (int j = 0; j < 4; j++) {
        int t = s - 3 + j;
        if (t >= 0) {
            const float* rp = base + (ptrdiff_t)(j - 3) * FQ;
            aq = fmaf(cw[cq*4+j], rp[0],  aq);
            ak = fmaf(cw[ck*4+j], rp[DK], ak);
        }
    }
    aq = aq / (1.f + expf(-aq));   // silu
    ak = ak / (1.f + expf(-ak));
    float sq = aq*aq, sk = ak*ak;
#pragma unroll
    for (int off = 16; off; off >>= 1) {
        sq += __shfl_xor_sync(0xffffffffu, sq, off);
        sk += __shfl_xor_sync(0xffffffffu, sk, off);
    }
    __shared__ float red[8];
    int w = d >> 5, lane = d & 31;
    if (lane == 0) { red[w] = sq; red[4+w] = sk; }
    __syncthreads();
    float tq = red[0]+red[1]+red[2]+red[3];
    float tk = red[4]+red[5]+red[6]+red[7];
    size_t oi = (size_t)bs*HK*DK + hk*DK + d;
    qo[oi] = aq * rsqrtf(tq + EPS) * QSCALE;
    ko[oi] = ak * rsqrtf(tk + EPS);
}

// ------------- conv(K=4)+silu for v (elementwise) ---------------------------
__global__ __launch_bounds__(256) void conv_v_kernel(const float* __restrict__ qkvz,
        const float* __restrict__ cw, const float* __restrict__ cb,
        float* __restrict__ vo) {
    size_t idx = (size_t)blockIdx.x * 256 + threadIdx.x;   // bs*HV*DV + hv*DV + d
    int d  = (int)(idx % DV);
    int hv = (int)((idx / DV) % HV);
    ptrdiff_t bs = (ptrdiff_t)(idx / ((size_t)DV*HV));
    int s = (int)(bs % Sc);
    int c = 2*HK*DK + hv*DV + d;
    int hk = hv / Gc, gi = hv % Gc;
    int col = hk*ROWH + 2*DK + gi*DV + d;
    float acc = cb[c];
#pragma unroll
    for (int j = 0; j < 4; j++) {
        int t = s - 3 + j;
        if (t >= 0)
            acc = fmaf(cw[c*4+j], qkvz[(size_t)(bs + j - 3)*FQ + col], acc);
    }
    vo[idx] = acc / (1.f + expf(-acc));
}

// ------------- g = -exp(a_log)*softplus(a+dt), beta = sigmoid(b) ------------
__global__ __launch_bounds__(256) void gb_kernel(const float* __restrict__ ba,
        const float* __restrict__ a_log, const float* __restrict__ dt_bias,
        float* __restrict__ gg, float* __restrict__ bb) {
    int idx = blockIdx.x * 256 + threadIdx.x;   // bs*HV + hv
    if (idx >= BS*HV) return;
    int hv = idx % HV;
    int bs = idx / HV;
    int hk = hv / Gc, gi = hv % Gc;
    float bval = ba[(size_t)bs*FBA + hk*2*Gc + gi];
    float aval = ba[(size_t)bs*FBA + hk*2*Gc + Gc + gi];
    float xin = aval + dt_bias[hv];
    float sp = (xin > 20.f) ? xin : log1pf(expf(xin));
    gg[idx] = -expf(a_log[hv]) * sp;
    bb[idx] = 1.f / (1.f + expf(-bval));
}

// ------------- delta-rule recurrence: one CTA per (b,hv,v-slice of 64) ------
// 256 threads = 8 warps; warp w owns v-cols [w*8, w*8+8); lane owns k-rows
// {lane, lane+32, lane+64, lane+96}. State 4x8 floats in registers/thread.
constexpr int TCH = 32;
__global__ __launch_bounds__(256) void recur_kernel(const float* __restrict__ q,
        const float* __restrict__ k, const float* __restrict__ v,
        const float* __restrict__ g, const float* __restrict__ be,
        float* __restrict__ o) {
    int bid = blockIdx.x;
    int slice = bid & 1;
    int hv = (bid >> 1) & (HV - 1);
    int b  = bid >> 6;
    int hk = hv >> 1;       // G = 2
    int vs0 = slice * 64;
    __shared__ float sq[TCH][128];
    __shared__ float sk[TCH][128];
    __shared__ float sv[TCH][64];
    __shared__ float sg[TCH], sb[TCH];
    const int tid = threadIdx.x, lane = tid & 31, w = tid >> 5;
    const float* qb = q + ((size_t)b*Sc*HK + hk) * DK;
    const float* kb = k + ((size_t)b*Sc*HK + hk) * DK;
    const float* vb = v + ((size_t)b*Sc*HV + hv) * DV + vs0;
    const float* gp = g + (size_t)b*Sc*HV + hv;
    const float* bp = be + (size_t)b*Sc*HV + hv;
    float* ob = o + ((size_t)b*Sc*HV + hv) * DV + vs0;

    float St[4][8];
#pragma unroll
    for (int r = 0; r < 4; r++)
#pragma unroll
        for (int j = 0; j < 8; j++) St[r][j] = 0.f;

    for (int s0 = 0; s0 < Sc; s0 += TCH) {
        __syncthreads();   // previous chunk's consumers done before refill
        for (int i = tid; i < TCH*32; i += 256) {
            int t = i >> 5, c4 = (i & 31) * 4;
            *(float4*)&sq[t][c4] = *(const float4*)&qb[(size_t)(s0+t)*HK*DK + c4];
            *(float4*)&sk[t][c4] = *(const float4*)&kb[(size_t)(s0+t)*HK*DK + c4];
        }
        for (int i = tid; i < TCH*16; i += 256) {
            int t = i >> 4, c4 = (i & 15) * 4;
            *(float4*)&sv[t][c4] = *(const float4*)&vb[(size_t)(s0+t)*HV*DV + c4];
        }
        if (tid < TCH) {
            sg[tid] = gp[(size_t)(s0+tid)*HV];
            sb[tid] = bp[(size_t)(s0+tid)*HV];
        }
        __syncthreads();

        for (int t = 0; t < TCH; t++) {
            float dec = expf(sg[t]);
            float bt  = sb[t];
            float kr[4], qr[4];
#pragma unroll
            for (int r = 0; r < 4; r++) {
                kr[r] = sk[t][lane + 32*r];
                qr[r] = sq[t][lane + 32*r];
            }
            // phase 1: decay + kS = k . S
            float kS[8];
#pragma unroll
            for (int j = 0; j < 8; j++) {
                float acc = 0.f;
#pragma unroll
                for (int r = 0; r < 4; r++) {
                    St[r][j] *= dec;
                    acc = fmaf(kr[r], St[r][j], acc);
                }
#pragma unroll
                for (int off = 16; off; off >>= 1)
                    acc += __shfl_xor_sync(0xffffffffu, acc, off);
                kS[j] = acc;
            }
            // phase 2: S += k (x) dv ;  o = q . S
            float myO = 0.f;
#pragma unroll
            for (int j = 0; j < 8; j++) {
                float dv = bt * (sv[t][w*8 + j] - kS[j]);
                float acc = 0.f;
#pragma unroll
                for (int r = 0; r < 4; r++) {
                    St[r][j] = fmaf(kr[r], dv, St[r][j]);
                    acc = fmaf(qr[r], St[r][j], acc);
                }
#pragma unroll
                for (int off = 16; off; off >>= 1)
                    acc += __shfl_xor_sync(0xffffffffu, acc, off);
                if (lane == j) myO = acc;
            }
            if (lane < 8)
                ob[(size_t)(s0+t)*HV*DV + w*8 + lane] = myO;   // 32B/warp sector
        }
    }
}

// ------------- y = o*silu(z); RMSNorm over DV (in place into o) -------------
__global__ __launch_bounds__(128) void ynorm_kernel(const float* __restrict__ qkvz,
        const float* __restrict__ nw, float* __restrict__ o) {
    int bsh = blockIdx.x;              // bs*HV + hv
    int hv = bsh & (HV - 1);
    int bs = bsh >> 5;
    int d = threadIdx.x;
    int hk = hv >> 1, gi = hv & 1;
    float z = qkvz[(size_t)bs*FQ + hk*ROWH + 2*DK + Gc*DV + gi*DV + d];
    size_t oi = (size_t)bsh*DV + d;
    float y = o[oi] * (z / (1.f + expf(-z)));
    float ss = y*y;
#pragma unroll
    for (int off = 16; off; off >>= 1) ss += __shfl_xor_sync(0xffffffffu, ss, off);
    __shared__ float red[4];
    int wdx = d >> 5, lane = d & 31;
    if (lane == 0) red[wdx] = ss;
    __syncthreads();
    float var = (red[0]+red[1]+red[2]+red[3]) * (1.f/DV);
    o[oi] = y * rsqrtf(var + EPS) * nw[d];
}

// ---------------------------------------------------------------------------
extern "C" void kernel_launch(void* const* d_in, const int* in_sizes, int n_in,
                              void* d_out, int out_size) {
    const float* x       = (const float*)d_in[0];
    const float* w_qkvz  = (const float*)d_in[1];
    const float* w_ba    = (const float*)d_in[2];
    const float* conv_w  = (const float*)d_in[3];
    const float* conv_b  = (const float*)d_in[4];
    const float* a_log   = (const float*)d_in[5];
    const float* dt_bias = (const float*)d_in[6];
    const float* norm_w  = (const float*)d_in[7];
    const float* w_o     = (const float*)d_in[8];
    float* out = (float*)d_out;

    float *qkvz, *ba, *q, *k, *v, *gg, *bb, *o;
    cudaGetSymbolAddress((void**)&qkvz, g_qkvz);
    cudaGetSymbolAddress((void**)&ba,   g_ba);
    cudaGetSymbolAddress((void**)&q,    g_q);
    cudaGetSymbolAddress((void**)&k,    g_k);
    cudaGetSymbolAddress((void**)&v,    g_v);
    cudaGetSymbolAddress((void**)&gg,   g_g);
    cudaGetSymbolAddress((void**)&bb,   g_b);
    cudaGetSymbolAddress((void**)&o,    g_o);

    // 1) big input projection + tiny ba projection
    sgemm128<false><<<dim3(FQ/128, BS/128), 256>>>(x, w_qkvz, qkvz, BS, FQ, Hc);
    sgemm128<true ><<<dim3(1,      BS/128), 256>>>(x, w_ba,   ba,   BS, FBA, Hc);

    // 2) conv + silu (+ l2norm for q,k), gate params
    conv_qk_kernel<<<BS*HK, 128>>>(qkvz, conv_w, conv_b, q, k);
    conv_v_kernel<<<(BS*HV*DV)/256, 256>>>(qkvz, conv_w, conv_b, v);
    gb_kernel<<<(BS*HV + 255)/256, 256>>>(ba, a_log, dt_bias, gg, bb);

    // 3) sequential delta-rule scan (128 CTAs: b x hv x 2 v-slices)
    recur_kernel<<<Bc*HV*2, 256>>>(q, k, v, gg, bb, o);

    // 4) gate + RMSNorm (in place), then output projection
    ynorm_kernel<<<BS*HV, 128>>>(qkvz, norm_w, o);
    sgemm128<false><<<dim3(Hc/128, BS/128), 256>>>(o, w_o, out, BS, Hc, HV*DV);
}

// round 2
// speedup vs baseline: 2.1351x; 2.1351x over previous
#include <cuda_runtime.h>
#include <math.h>
#include <stddef.h>
#include <stdint.h>

// ---------------------------------------------------------------------------
// GatedDeltaNet  B=2 S=2048 H=2048  HK=16 HV=32 DK=DV=128  conv K=4
// R2: big GEMMs -> TF32 tensor cores (mma.sync m16n8k8, cp.async pipeline)
// ---------------------------------------------------------------------------
namespace {
constexpr int Bc = 2, Sc = 2048, Hc = 2048;
constexpr int DK = 128, DV = 128, HK = 16, HV = 32, Gc = 2;
constexpr int FQ  = 2*HK*DK + 2*HV*DV;   // 12288
constexpr int FBA = 2*HV;                // 64
constexpr int ROWH = 2*DK + 2*Gc*DV;     // 768
constexpr int BS = Bc*Sc;                // 4096
constexpr float EPS = 1e-6f;
constexpr float QSCALE = 0.08838834764831845f;  // DK^-0.5
}

// ------------------------- scratch (static device mem) ---------------------
__device__ float g_qkvz[(size_t)BS*FQ];
__device__ float g_ba  [(size_t)BS*FBA];
__device__ float g_q   [(size_t)BS*HK*DK];
__device__ float g_k   [(size_t)BS*HK*DK];
__device__ float g_v   [(size_t)BS*HV*DV];
__device__ float g_g   [(size_t)BS*HV];
__device__ float g_b   [(size_t)BS*HV];
__device__ float g_o   [(size_t)BS*HV*DV];

// ======================= TF32 tensor-core GEMM ==============================
// C[M,N] = A[M,K] @ B[K,N], all fp32 row-major, M,N,K multiples of 128/128/32.
// Block tile 128x128x32, 8 warps (2x4), warp tile 64x32, mma.m16n8k8.tf32.
// Smem: As[128][36] (banks 4m+k, conflict-free), Bs[32][136] (banks 8k+n).
namespace tfg {
constexpr int BM = 128, BN = 128, BK = 32;
constexpr int APAD = 36;    // floats per A row  (144B, 16B-aligned)
constexpr int BPAD = 136;   // floats per B row  (544B, 16B-aligned)
constexpr int ASZ = BM * APAD;   // 4608 floats
constexpr int BSZ = BK * BPAD;   // 4352 floats
constexpr int SMEM_FLOATS = 2 * (ASZ + BSZ);     // 17920 floats = 71680 B
}

__device__ __forceinline__ uint32_t f2tf32(float x) {
    uint32_t r;
    asm("cvt.rna.tf32.f32 %0, %1;" : "=r"(r) : "f"(x));
    return r;
}
__device__ __forceinline__ void cp16(void* sdst, const void* gsrc) {
    uint32_t s = (uint32_t)__cvta_generic_to_shared(sdst);
    asm volatile("cp.async.cg.shared.global [%0], [%1], 16;" :: "r"(s), "l"(gsrc));
}
__device__ __forceinline__ void cp_commit() {
    asm volatile("cp.async.commit_group;");
}
template<int N>
__device__ __forceinline__ void cp_wait() {
    asm volatile("cp.async.wait_group %0;" :: "n"(N));
}
__device__ __forceinline__ void mma_tf32(float* d, const uint32_t* a, const uint32_t* b) {
    asm volatile(
        "mma.sync.aligned.m16n8k8.row.col.f32.tf32.tf32.f32 "
        "{%0,%1,%2,%3},{%4,%5,%6,%7},{%8,%9},{%0,%1,%2,%3};"
        : "+f"(d[0]), "+f"(d[1]), "+f"(d[2]), "+f"(d[3])
        : "r"(a[0]), "r"(a[1]), "r"(a[2]), "r"(a[3]), "r"(b[0]), "r"(b[1]));
}

__global__ __launch_bounds__(256, 2) void gemm_tf32(const float* __restrict__ A,
                                                    const float* __restrict__ B,
                                                    float* __restrict__ C,
                                                    int M, int N, int K) {
    using namespace tfg;
    extern __shared__ float sm[];
    float* As[2] = { sm,                sm + ASZ };
    float* Bs[2] = { sm + 2*ASZ,        sm + 2*ASZ + BSZ };

    const int tid  = threadIdx.x;
    const int lane = tid & 31;
    const int wid  = tid >> 5;
    const int warpM = wid >> 2;              // 0..1
    const int warpN = wid & 3;               // 0..3
    const int mw = warpM * 64;
    const int nw = warpN * 32;
    const int r = lane >> 2;                 // groupID
    const int c = lane & 3;                  // threadID_in_group
    const int bm = blockIdx.y * BM;
    const int bn = blockIdx.x * BN;

    // global->smem indices (4 x 16B each for A and B per thread)
    const int aRow = tid >> 1;                    // stride 128 over i? no:
    // A tile: 128 rows x 32 cols = 1024 float4.  idx = tid + 256*i
    // row = idx>>3, col4 = (idx&7)*4
    // B tile: 32 rows x 128 cols = 1024 float4.  row = idx>>5, col4 = (idx&31)*4
    (void)aRow;

    float acc[4][4][4];
#pragma unroll
    for (int i = 0; i < 4; i++)
#pragma unroll
        for (int j = 0; j < 4; j++)
#pragma unroll
            for (int e = 0; e < 4; e++) acc[i][j][e] = 0.f;

    const int ntiles = K / BK;

    auto issue_tile = [&](int t, int st) {
#pragma unroll
        for (int i = 0; i < 4; i++) {
            int idx = tid + 256 * i;
            int row = idx >> 3, c4 = (idx & 7) << 2;
            cp16(As[st] + row * APAD + c4,
                 A + (size_t)(bm + row) * K + t * BK + c4);
        }
#pragma unroll
        for (int i = 0; i < 4; i++) {
            int idx = tid + 256 * i;
            int row = idx >> 5, c4 = (idx & 31) << 2;
            cp16(Bs[st] + row * BPAD + c4,
                 B + (size_t)(t * BK + row) * N + bn + c4);
        }
        cp_commit();
    };

    issue_tile(0, 0);

    for (int t = 0; t < ntiles; t++) {
        const int st = t & 1;
        if (t + 1 < ntiles) {
            issue_tile(t + 1, st ^ 1);
            cp_wait<1>();
        } else {
            cp_wait<0>();
        }
        __syncthreads();

        const float* Ab = As[st];
        const float* Bb = Bs[st];
#pragma unroll
        for (int kk = 0; kk < 4; kk++) {
            const int k0 = kk * 8;
            uint32_t af[4][4];
#pragma unroll
            for (int i = 0; i < 4; i++) {
                const float* p = Ab + (mw + 16*i + r) * APAD + k0 + c;
                af[i][0] = f2tf32(p[0]);
                af[i][1] = f2tf32(p[8 * APAD]);
                af[i][2] = f2tf32(p[4]);
                af[i][3] = f2tf32(p[8 * APAD + 4]);
            }
            uint32_t bf[4][2];
#pragma unroll
            for (int j = 0; j < 4; j++) {
                const float* p = Bb + (k0 + c) * BPAD + nw + 8*j + r;
                bf[j][0] = f2tf32(p[0]);
                bf[j][1] = f2tf32(p[4 * BPAD]);
            }
#pragma unroll
            for (int i = 0; i < 4; i++)
#pragma unroll
                for (int j = 0; j < 4; j++)
                    mma_tf32(acc[i][j], af[i], bf[j]);
        }
        __syncthreads();
    }

    // epilogue: c0,c1 -> (row, 2c),(row, 2c+1); c2,c3 -> row+8
#pragma unroll
    for (int i = 0; i < 4; i++) {
#pragma unroll
        for (int j = 0; j < 4; j++) {
            int row = bm + mw + 16*i + r;
            int col = bn + nw + 8*j + 2*c;
            *(float2*)&C[(size_t)row * N + col] =
                make_float2(acc[i][j][0], acc[i][j][1]);
            *(float2*)&C[(size_t)(row + 8) * N + col] =
                make_float2(acc[i][j][2], acc[i][j][3]);
        }
    }
}

// ------------------------- fp32 SGEMM (kept for tiny ba GEMM) --------------
template<bool GN>
__global__ __launch_bounds__(256) void sgemm128(const float* __restrict__ A,
                                                const float* __restrict__ B,
                                                float* __restrict__ C,
                                                int M, int N, int K) {
    __shared__ float As[8][128];
    __shared__ float Bs[8][128];
    const int tid = threadIdx.x;
    const int bn = blockIdx.x * 128;
    const int bm = blockIdx.y * 128;
    const int tr = (tid >> 4) * 8;
    const int tc = (tid & 15) * 8;
    const int aRow = tid >> 1, aCol = (tid & 1) * 4;
    const int bRow = tid >> 5, bCol = (tid & 31) * 4;
    const float* Ag = A + (size_t)(bm + aRow) * K + aCol;
    const float* Bg = B + (size_t)bRow * N + bn + bCol;
    float acc[8][8];
#pragma unroll
    for (int i = 0; i < 8; i++)
#pragma unroll
        for (int j = 0; j < 8; j++) acc[i][j] = 0.f;

    for (int k0 = 0; k0 < K; k0 += 8) {
        float4 av = *(const float4*)(Ag + k0);
        As[aCol+0][aRow] = av.x; As[aCol+1][aRow] = av.y;
        As[aCol+2][aRow] = av.z; As[aCol+3][aRow] = av.w;
        float4 bv = make_float4(0.f, 0.f, 0.f, 0.f);
        if (!GN || (bn + bCol) < N) bv = *(const float4*)(Bg + (size_t)k0 * N);
        *(float4*)&Bs[bRow][bCol] = bv;
        __syncthreads();
#pragma unroll
        for (int kk = 0; kk < 8; kk++) {
            float4 a0 = *(const float4*)&As[kk][tr];
            float4 a1 = *(const float4*)&As[kk][tr+4];
            float4 b0 = *(const float4*)&Bs[kk][tc];
            float4 b1 = *(const float4*)&Bs[kk][tc+4];
            float a[8]  = {a0.x,a0.y,a0.z,a0.w,a1.x,a1.y,a1.z,a1.w};
            float bb[8] = {b0.x,b0.y,b0.z,b0.w,b1.x,b1.y,b1.z,b1.w};
#pragma unroll
            for (int i = 0; i < 8; i++)
#pragma unroll
                for (int j = 0; j < 8; j++) acc[i][j] = fmaf(a[i], bb[j], acc[i][j]);
        }
        __syncthreads();
    }
#pragma unroll
    for (int i = 0; i < 8; i++) {
        size_t row = (size_t)(bm + tr + i);
#pragma unroll
        for (int j = 0; j < 8; j += 4) {
            if (!GN || (bn + tc + j) < N)
                *(float4*)&C[row * N + bn + tc + j] =
                    make_float4(acc[i][j], acc[i][j+1], acc[i][j+2], acc[i][j+3]);
        }
    }
}

// ------------- conv(K=4)+silu+l2norm for q,k (one block per b,s,hk) --------
__global__ __launch_bounds__(128) void conv_qk_kernel(const float* __restrict__ qkvz,
        const float* __restrict__ cw, const float* __restrict__ cb,
        float* __restrict__ qo, float* __restrict__ ko) {
    int bsh = blockIdx.x;
    int hk = bsh % HK;
    int bs = bsh / HK;
    int s = bs % Sc;
    int d = threadIdx.x;
    int cq = hk*DK + d;
    int ck = HK*DK + cq;
    const float* base = qkvz + (size_t)bs*FQ + hk*ROWH + d;
    float aq = cb[cq], ak = cb[ck];
#pragma unroll
    for (int j = 0; j < 4; j++) {
        int t = s - 3 + j;
        if (t >= 0) {
            const float* rp = base + (ptrdiff_t)(j - 3) * FQ;
            aq = fmaf(cw[cq*4+j], rp[0],  aq);
            ak = fmaf(cw[ck*4+j], rp[DK], ak);
        }
    }
    aq = aq / (1.f + expf(-aq));   // silu
    ak = ak / (1.f + expf(-ak));
    float sq = aq*aq, sk = ak*ak;
#pragma unroll
    for (int off = 16; off; off >>= 1) {
        sq += __shfl_xor_sync(0xffffffffu, sq, off);
        sk += __shfl_xor_sync(0xffffffffu, sk, off);
    }
    __shared__ float red[8];
    int w = d >> 5, lane = d & 31;
    if (lane == 0) { red[w] = sq; red[4+w] = sk; }
    __syncthreads();
    float tq = red[0]+red[1]+red[2]+red[3];
    float tk = red[4]+red[5]+red[6]+red[7];
    size_t oi = (size_t)bs*HK*DK + hk*DK + d;
    qo[oi] = aq * rsqrtf(tq + EPS) * QSCALE;
    ko[oi] = ak * rsqrtf(tk + EPS);
}

// ------------- conv(K=4)+silu for v (elementwise) ---------------------------
__global__ __launch_bounds__(256) void conv_v_kernel(const float* __restrict__ qkvz,
        const float* __restrict__ cw, const float* __restrict__ cb,
        float* __restrict__ vo) {
    size_t idx = (size_t)blockIdx.x * 256 + threadIdx.x;
    int d  = (int)(idx % DV);
    int hv = (int)((idx / DV) % HV);
    ptrdiff_t bs = (ptrdiff_t)(idx / ((size_t)DV*HV));
    int s = (int)(bs % Sc);
    int ccol = 2*HK*DK + hv*DV + d;
    int hk = hv / Gc, gi = hv % Gc;
    int col = hk*ROWH + 2*DK + gi*DV + d;
    float acc = cb[ccol];
#pragma unroll
    for (int j = 0; j < 4; j++) {
        int t = s - 3 + j;
        if (t >= 0)
            acc = fmaf(cw[ccol*4+j], qkvz[(size_t)(bs + j - 3)*FQ + col], acc);
    }
    vo[idx] = acc / (1.f + expf(-acc));
}

// ------------- g = -exp(a_log)*softplus(a+dt), beta = sigmoid(b) ------------
__global__ __launch_bounds__(256) void gb_kernel(const float* __restrict__ ba,
        const float* __restrict__ a_log, const float* __restrict__ dt_bias,
        float* __restrict__ gg, float* __restrict__ bb) {
    int idx = blockIdx.x * 256 + threadIdx.x;
    if (idx >= BS*HV) return;
    int hv = idx % HV;
    int bs = idx / HV;
    int hk = hv / Gc, gi = hv % Gc;
    float bval = ba[(size_t)bs*FBA + hk*2*Gc + gi];
    float aval = ba[(size_t)bs*FBA + hk*2*Gc + Gc + gi];
    float xin = aval + dt_bias[hv];
    float sp = (xin > 20.f) ? xin : log1pf(expf(xin));
    gg[idx] = -expf(a_log[hv]) * sp;
    bb[idx] = 1.f / (1.f + expf(-bval));
}

// ------------- delta-rule recurrence: one CTA per (b,hv,v-slice of 64) ------
constexpr int TCH = 32;
__global__ __launch_bounds__(256) void recur_kernel(const float* __restrict__ q,
        const float* __restrict__ k, const float* __restrict__ v,
        const float* __restrict__ g, const float* __restrict__ be,
        float* __restrict__ o) {
    int bid = blockIdx.x;
    int slice = bid & 1;
    int hv = (bid >> 1) & (HV - 1);
    int b  = bid >> 6;
    int hk = hv >> 1;
    int vs0 = slice * 64;
    __shared__ float sq[TCH][128];
    __shared__ float sk[TCH][128];
    __shared__ float sv[TCH][64];
    __shared__ float sg[TCH], sb[TCH];
    const int tid = threadIdx.x, lane = tid & 31, w = tid >> 5;
    const float* qb = q + ((size_t)b*Sc*HK + hk) * DK;
    const float* kb = k + ((size_t)b*Sc*HK + hk) * DK;
    const float* vb = v + ((size_t)b*Sc*HV + hv) * DV + vs0;
    const float* gp = g + (size_t)b*Sc*HV + hv;
    const float* bp = be + (size_t)b*Sc*HV + hv;
    float* ob = o + ((size_t)b*Sc*HV + hv) * DV + vs0;

    float St[4][8];
#pragma unroll
    for (int rr = 0; rr < 4; rr++)
#pragma unroll
        for (int j = 0; j < 8; j++) St[rr][j] = 0.f;

    for (int s0 = 0; s0 < Sc; s0 += TCH) {
        __syncthreads();
        for (int i = tid; i < TCH*32; i += 256) {
            int t = i >> 5, c4 = (i & 31) * 4;
            *(float4*)&sq[t][c4] = *(const float4*)&qb[(size_t)(s0+t)*HK*DK + c4];
            *(float4*)&sk[t][c4] = *(const float4*)&kb[(size_t)(s0+t)*HK*DK + c4];
        }
        for (int i = tid; i < TCH*16; i += 256) {
            int t = i >> 4, c4 = (i & 15) * 4;
            *(float4*)&sv[t][c4] = *(const float4*)&vb[(size_t)(s0+t)*HV*DV + c4];
        }
        if (tid < TCH) {
            sg[tid] = gp[(size_t)(s0+tid)*HV];
            sb[tid] = bp[(size_t)(s0+tid)*HV];
        }
        __syncthreads();

        for (int t = 0; t < TCH; t++) {
            float dec = expf(sg[t]);
            float bt  = sb[t];
            float kr[4], qr[4];
#pragma unroll
            for (int rr = 0; rr < 4; rr++) {
                kr[rr] = sk[t][lane + 32*rr];
                qr[rr] = sq[t][lane + 32*rr];
            }
            float kS[8];
#pragma unroll
            for (int j = 0; j < 8; j++) {
                float acc = 0.f;
#pragma unroll
                for (int rr = 0; rr < 4; rr++) {
                    St[rr][j] *= dec;
                    acc = fmaf(kr[rr], St[rr][j], acc);
                }
#pragma unroll
                for (int off = 16; off; off >>= 1)
                    acc += __shfl_xor_sync(0xffffffffu, acc, off);
                kS[j] = acc;
            }
            float myO = 0.f;
#pragma unroll
            for (int j = 0; j < 8; j++) {
                float dv = bt * (sv[t][w*8 + j] - kS[j]);
                float acc = 0.f;
#pragma unroll
                for (int rr = 0; rr < 4; rr++) {
                    St[rr][j] = fmaf(kr[rr], dv, St[rr][j]);
                    acc = fmaf(qr[rr], St[rr][j], acc);
                }
#pragma unroll
                for (int off = 16; off; off >>= 1)
                    acc += __shfl_xor_sync(0xffffffffu, acc, off);
                if (lane == j) myO = acc;
            }
            if (lane < 8)
                ob[(size_t)(s0+t)*HV*DV + w*8 + lane] = myO;
        }
    }
}

// ------------- y = o*silu(z); RMSNorm over DV (in place into o) -------------
__global__ __launch_bounds__(128) void ynorm_kernel(const float* __restrict__ qkvz,
        const float* __restrict__ nw, float* __restrict__ o) {
    int bsh = blockIdx.x;
    int hv = bsh & (HV - 1);
    int bs = bsh >> 5;
    int d = threadIdx.x;
    int hk = hv >> 1, gi = hv & 1;
    float z = qkvz[(size_t)bs*FQ + hk*ROWH + 2*DK + Gc*DV + gi*DV + d];
    size_t oi = (size_t)bsh*DV + d;
    float y = o[oi] * (z / (1.f + expf(-z)));
    float ss = y*y;
#pragma unroll
    for (int off = 16; off; off >>= 1) ss += __shfl_xor_sync(0xffffffffu, ss, off);
    __shared__ float red[4];
    int wdx = d >> 5, lane = d & 31;
    if (lane == 0) red[wdx] = ss;
    __syncthreads();
    float var = (red[0]+red[1]+red[2]+red[3]) * (1.f/DV);
    o[oi] = y * rsqrtf(var + EPS) * nw[d];
}

// ---------------------------------------------------------------------------
extern "C" void kernel_launch(void* const* d_in, const int* in_sizes, int n_in,
                              void* d_out, int out_size) {
    const float* x       = (const float*)d_in[0];
    const float* w_qkvz  = (const float*)d_in[1];
    const float* w_ba    = (const float*)d_in[2];
    const float* conv_w  = (const float*)d_in[3];
    const float* conv_b  = (const float*)d_in[4];
    const float* a_log   = (const float*)d_in[5];
    const float* dt_bias = (const float*)d_in[6];
    const float* norm_w  = (const float*)d_in[7];
    const float* w_o     = (const float*)d_in[8];
    float* out = (float*)d_out;

    float *qkvz, *ba, *q, *k, *v, *gg, *bb, *o;
    cudaGetSymbolAddress((void**)&qkvz, g_qkvz);
    cudaGetSymbolAddress((void**)&ba,   g_ba);
    cudaGetSymbolAddress((void**)&q,    g_q);
    cudaGetSymbolAddress((void**)&k,    g_k);
    cudaGetSymbolAddress((void**)&v,    g_v);
    cudaGetSymbolAddress((void**)&gg,   g_g);
    cudaGetSymbolAddress((void**)&bb,   g_b);
    cudaGetSymbolAddress((void**)&o,    g_o);

    const int smem_bytes = tfg::SMEM_FLOATS * sizeof(float);   // 71680
    cudaFuncSetAttribute(gemm_tf32, cudaFuncAttributeMaxDynamicSharedMemorySize,
                         smem_bytes);

    // 1) big input projection (TF32 TC) + tiny ba projection (fp32)
    gemm_tf32<<<dim3(FQ/128, BS/128), 256, smem_bytes>>>(x, w_qkvz, qkvz, BS, FQ, Hc);
    sgemm128<true><<<dim3(1, BS/128), 256>>>(x, w_ba, ba, BS, FBA, Hc);

    // 2) conv + silu (+ l2norm for q,k), gate params
    conv_qk_kernel<<<BS*HK, 128>>>(qkvz, conv_w, conv_b, q, k);
    conv_v_kernel<<<(BS*HV*DV)/256, 256>>>(qkvz, conv_w, conv_b, v);
    gb_kernel<<<(BS*HV + 255)/256, 256>>>(ba, a_log, dt_bias, gg, bb);

    // 3) sequential delta-rule scan
    recur_kernel<<<Bc*HV*2, 256>>>(q, k, v, gg, bb, o);

    // 4) gate + RMSNorm, then output projection (TF32 TC)
    ynorm_kernel<<<BS*HV, 128>>>(qkvz, norm_w, o);
    gemm_tf32<<<dim3(Hc/128, BS/128), 256, smem_bytes>>>(o, w_o, out, BS, Hc, HV*DV);
}